// round 15
// baseline (speedup 1.0000x reference)
#include <cuda_runtime.h>

#define NL     32
#define NF     720
#define DTF    60.0f
#define SCALE  256.0f
#define CLM    23          // modal chunk length (32 warps: 31*23 + 6 = 719)
#define NCHM   32
#define TBLK   1024
#define GRID2  24          // block 0 = modal, blocks 1..23 = transform (23*32=736)

typedef unsigned long long u64;
#define FULL 0xffffffffu

// Persistent scratch
__device__ float    g_A  [NL * NL];   // A[l*32+r] = Q[r][l] / d_r
__device__ float2   g_Lam[NL];
__device__ float2   g_G0u[NL];        // unscaled forcing coeffs
__device__ float2   g_G1u[NL];
__device__ float    g_sc [NL];        // per-mode forcing scale (DT*Kin0*v0)
__device__ float2   g_Z  [NF * NL];
__device__ unsigned g_flag;

// ---- packed f32x2 helpers ---------------------------------------------------
__device__ __forceinline__ u64 pk2(float lo, float hi) {
    u64 r; asm("mov.b64 %0, {%1, %2};" : "=l"(r) : "f"(lo), "f"(hi)); return r;
}
__device__ __forceinline__ void upk2(float& lo, float& hi, u64 v) {
    asm("mov.b64 {%0, %1}, %2;" : "=f"(lo), "=f"(hi) : "l"(v));
}
__device__ __forceinline__ void ffma2(u64& d, u64 a, u64 b) {
    asm("fma.rn.f32x2 %0, %1, %2, %3;" : "=l"(d) : "l"(a), "l"(b), "l"(d));
}
__device__ __forceinline__ float frcpa(float x) {
    float r; asm("rcp.approx.f32 %0, %1;" : "=f"(r) : "f"(x)); return r;
}
__device__ __forceinline__ float2 cmulf(float2 a, float2 b) {
    return make_float2(a.x * b.x - a.y * b.y, a.x * b.y + a.y * b.x);
}

// Sturm count with 4-step batched rescaling (sign-preserving)
__device__ __forceinline__ int sturm_count(float x,
                                           const float* __restrict__ ch,
                                           const float* __restrict__ s2h)
{
    float p0 = 1.0f;
    float p1 = ch[0] - x;
    bool  s1 = (p1 < 0.0f) || (p1 == 0.0f);
    int   cnt = s1 ? 1 : 0;
    #pragma unroll
    for (int r = 1; r < NL; ++r) {
        float p2 = fmaf(ch[r] - x, p1, -s2h[r] * p0);
        bool sg = (p2 < 0.0f);
        if (p2 == 0.0f) sg = !s1;
        cnt += (sg != s1) ? 1 : 0;
        p0 = p1; p1 = p2; s1 = sg;
        if ((r & 3) == 3) {
            float m  = fmaxf(fmaxf(fabsf(p0), fabsf(p1)), 1e-30f);
            float sc = frcpa(m);
            p0 *= sc; p1 *= sc;
        }
    }
    return cnt;
}

// ---------------------------------------------------------------------------
// Kernel 1: eigen solve. 32 blocks x 64 threads (2 warps). (R14, 4 bisection rounds)
// ---------------------------------------------------------------------------
__global__ void __launch_bounds__(64, 1)
eigen_kernel(const float* __restrict__ pk, const float* __restrict__ fc)
{
    __shared__ float ch [NL];
    __shared__ float sh [NL];
    __shared__ float s2h[NL];
    __shared__ float vsm[NL];

    const int tid  = threadIdx.x;
    const int lane = tid & 31;
    const int w    = tid >> 5;
    const int l    = blockIdx.x;

    if (l == 0 && tid == 0) g_flag = 0;

    float dinv = 0.0f;
    if (w == 0) {
        const float kin  = expf(pk[2 * lane]);
        const float kout = expf(pk[2 * lane + 1]);
        float t = (lane > 0) ? 0.5f * (pk[2 * lane - 1] - pk[2 * lane]) : 0.0f;
        #pragma unroll
        for (int o = 1; o < 32; o <<= 1) {
            float u = __shfl_up_sync(FULL, t, o);
            if (lane >= o) t += u;
        }
        dinv = expf(-t);

        const float c = -DTF * (((lane > 0) ? kin : 0.0f) + kout) * SCALE;
        const float s = (lane > 0)
            ? DTF * expf(0.5f * (pk[2 * lane] + pk[2 * lane - 1])) * SCALE
            : 0.0f;
        ch[lane]  = c;
        sh[lane]  = s;
        s2h[lane] = s * s;
    }
    __syncthreads();

    // bisection (both warps)
    const float c_  = ch[lane];
    const float s_  = sh[lane];
    const float op_ = (lane < NL - 1) ? sh[lane + 1] : 0.0f;
    float rad = s_ + op_;
    float lo  = c_ - rad, hi = c_ + rad;
    #pragma unroll
    for (int o = 16; o > 0; o >>= 1) {
        lo = fminf(lo, __shfl_xor_sync(FULL, lo, o));
        hi = fmaxf(hi, __shfl_xor_sync(FULL, hi, o));
    }
    float width = hi - lo;
    float a_ = lo - 1e-6f * (fabsf(width) + 1.0f);
    float b_ = hi + 1e-6f * (fabsf(width) + 1.0f);

    for (int round = 0; round < 4; ++round) {
        float x = a_ + (b_ - a_) * (float)(lane + 1) * (1.0f / 33.0f);
        int cnt = sturm_count(x, ch, s2h);
        unsigned mask = __ballot_sync(FULL, cnt <= l);
        if (mask) {
            int j = 31 - __clz((int)mask);
            float na = __shfl_sync(FULL, x, j);
            float nb = (j < 31) ? __shfl_sync(FULL, x, j + 1) : b_;
            a_ = na; b_ = nb;
        } else {
            b_ = __shfl_sync(FULL, x, 0);
        }
    }
    const float xhat = 0.5f * (a_ + b_);

    if (w == 0) {
        if (lane == 0) {
            float rp[NL];
            {
                float dd = ch[0] - xhat;
                dd = copysignf(fmaxf(fabsf(dd), 1e-12f), dd);
                rp[0] = frcpa(dd);
                #pragma unroll
                for (int r = 1; r < NL; ++r) {
                    dd = fmaf(-s2h[r], rp[r - 1], ch[r] - xhat);
                    dd = copysignf(fmaxf(fabsf(dd), 1e-12f), dd);
                    rp[r] = frcpa(dd);
                }
            }
            float vb[NL];
            #pragma unroll
            for (int r = 0; r < NL; ++r) vb[r] = 1.0f;

            #pragma unroll
            for (int it = 0; it < 2; ++it) {
                float wk[NL];
                wk[0] = vb[0];
                #pragma unroll
                for (int r = 1; r < NL; ++r)
                    wk[r] = fmaf(-sh[r] * rp[r - 1], wk[r - 1], vb[r]);
                wk[NL - 1] = wk[NL - 1] * rp[NL - 1];
                #pragma unroll
                for (int r = NL - 2; r >= 0; --r)
                    wk[r] = (wk[r] - sh[r + 1] * wk[r + 1]) * rp[r];

                float m = 1e-30f;
                #pragma unroll
                for (int r = 0; r < NL; ++r) m = fmaxf(m, fabsf(wk[r]));
                float im = frcpa(m);
                #pragma unroll
                for (int r = 0; r < NL; ++r) vb[r] = wk[r] * im;
            }
            #pragma unroll
            for (int r = 0; r < NL; ++r) vsm[r] = vb[r];
        }
        __syncwarp();

        float v  = vsm[lane];
        float n2 = v * v;
        #pragma unroll
        for (int o = 16; o > 0; o >>= 1) n2 += __shfl_xor_sync(FULL, n2, o);
        float inv = rsqrtf(n2);
        g_A[l * NL + lane] = v * inv * dinv;
        float v0n = __shfl_sync(FULL, v, 0) * inv;
        if (lane == 0) g_sc[l] = DTF * expf(pk[0]) * v0n;
    } else if (lane == 0) {
        const double mur = (double)xhat * (1.0 / (double)SCALE);
        const double mui = -(double)DTF * (double)fc[0];
        const double br  = 1.0 + mur, bi = mui;

        double b2r  = br * br - bi * bi,     b2i  = 2.0 * br * bi;
        double b4r  = b2r * b2r - b2i * b2i, b4i  = 2.0 * b2r * b2i;
        double b8r  = b4r * b4r - b4i * b4i, b8i  = 2.0 * b4r * b4i;
        double b16r = b8r * b8r - b8i * b8i, b16i = 2.0 * b8r * b8i;
        double b32r = b16r * b16r - b16i * b16i, b32i = 2.0 * b16r * b16i;

        double Lr = b32r * b16r - b32i * b16i;
        double Li = b32r * b16i + b32i * b16r;
        { double tr = Lr * b8r - Li * b8i; Li = Lr * b8i + Li * b8r; Lr = tr; }
        { double tr = Lr * b4r - Li * b4i; Li = Lr * b4i + Li * b4r; Lr = tr; }

        double mLr = mur * Lr - mui * Li;
        double mLi = mur * Li + mui * Lr;
        double n0r = 1.0 - Lr + 60.0 * mLr, n0i = -Li + 60.0 * mLi;
        double n1r = Lr - 1.0 - 60.0 * mur, n1i = Li - 60.0 * mui;
        double m2r = mur * mur - mui * mui, m2i = 2.0 * mur * mui;
        double dr  = 60.0 * m2r, di = 60.0 * m2i;
        double idn = 1.0 / (dr * dr + di * di);
        double G0r = (n0r * dr + n0i * di) * idn;
        double G0i = (n0i * dr - n0r * di) * idn;
        double G1r = (n1r * dr + n1i * di) * idn;
        double G1i = (n1i * dr - n1r * di) * idn;

        g_Lam[l] = make_float2((float)Lr,  (float)Li);
        g_G0u[l] = make_float2((float)G0r, (float)G0i);
        g_G1u[l] = make_float2((float)G1r, (float)G1i);
    }
}

// ---------------------------------------------------------------------------
// Kernel 2: fused modal + transform. 24 blocks x 1024 threads.
//   block 0   : tau staged in smem, 32-warp modal scan (depth 23+31+23)
//   blocks 1+ : transform 32 timesteps each (thread = (k, row))
// ---------------------------------------------------------------------------
__global__ void __launch_bounds__(TBLK, 1)
main2_kernel(const float* __restrict__ TAx, const float* __restrict__ TAy,
             float* __restrict__ out)
{
    const int tid = threadIdx.x;

    if (blockIdx.x == 0) {
        __shared__ float  stx[NF], sty[NF];
        __shared__ float2 zloc[NCHM][NL];
        __shared__ float2 carr[NCHM][NL];

        // bulk-stage tau (coalesced, off the scan chain)
        if (tid < NF) { stx[tid] = TAx[tid]; sty[tid] = TAy[tid]; }
        __syncthreads();

        const int l = tid & 31;
        const int c = tid >> 5;                  // 0..31

        const float2 L  = g_Lam[l];
        const float  sc = g_sc[l];
        float2 G0 = g_G0u[l]; G0.x *= sc; G0.y *= sc;
        float2 G1 = g_G1u[l]; G1.x *= sc; G1.y *= sc;

        const int k0  = c * CLM;
        const int len = min(CLM, (NF - 1) - k0);   // 23, last chunk 6

        float zr = 0.0f, zi = 0.0f;
        {
            float txa = stx[k0], tya = sty[k0];
            for (int m = 0; m < len; ++m) {
                const int k = k0 + m;
                float txb = stx[k + 1], tyb = sty[k + 1];
                float fr = txa * G0.x - tya * G0.y + txb * G1.x - tyb * G1.y;
                float fi = txa * G0.y + tya * G0.x + txb * G1.y + tyb * G1.x;
                float nr = fr + L.x * zr - L.y * zi;
                float ni = fi + L.x * zi + L.y * zr;
                zr = nr; zi = ni;
                txa = txb; tya = tyb;
            }
        }
        zloc[c][l] = make_float2(zr, zi);
        __syncthreads();

        if (c == 0) {
            float2 base = L, pw = make_float2(1.0f, 0.0f);
            int e = CLM;
            while (e) { if (e & 1) pw = cmulf(pw, base); base = cmulf(base, base); e >>= 1; }

            float kr = 0.0f, ki = 0.0f;
            carr[0][l] = make_float2(0.0f, 0.0f);
            for (int cc = 0; cc < NCHM - 1; ++cc) {
                float2 sv = zloc[cc][l];
                float nr = pw.x * kr - pw.y * ki + sv.x;
                float ni = pw.x * ki + pw.y * kr + sv.y;
                kr = nr; ki = ni;
                carr[cc + 1][l] = make_float2(kr, ki);
            }
        }
        __syncthreads();

        {
            float2 K = carr[c][l];
            zr = K.x; zi = K.y;
            float txa = stx[k0], tya = sty[k0];
            for (int m = 0; m < len; ++m) {
                const int k = k0 + m;
                float txb = stx[k + 1], tyb = sty[k + 1];
                float fr = txa * G0.x - tya * G0.y + txb * G1.x - tyb * G1.y;
                float fi = txa * G0.y + tya * G0.x + txb * G1.y + tyb * G1.x;
                float nr = fr + L.x * zr - L.y * zi;
                float ni = fi + L.x * zi + L.y * zr;
                zr = nr; zi = ni;
                txa = txb; tya = tyb;
                g_Z[(k + 1) * NL + l] = make_float2(zr, zi);
            }
        }
        __syncthreads();
        __threadfence();
        if (tid == 0) atomicExch(&g_flag, 1);
    } else {
        __shared__ float  As[NL * NL];
        __shared__ float2 Zs[32 * NL];

        for (int i = tid; i < NL * NL; i += TBLK) As[i] = g_A[i];   // pre-spin

        if (tid == 0)
            while (atomicAdd(&g_flag, 0) == 0) __nanosleep(32);
        __syncthreads();
        __threadfence();

        const int kbase = (blockIdx.x - 1) * 32;
        {
            int kk = tid >> 5, li = tid & 31;
            int k = kbase + kk;
            Zs[tid] = (k >= 1 && k < NF) ? g_Z[k * NL + li] : make_float2(0.0f, 0.0f);
        }
        __syncthreads();

        const int kk = tid >> 5, r = tid & 31;
        const int k  = kbase + kk;
        if (k >= NF) return;

        const u64* zv = reinterpret_cast<const u64*>(&Zs[kk * NL]);
        u64 acc = 0ull;
        #pragma unroll
        for (int li = 0; li < NL; ++li) {
            float a = As[li * NL + r];
            ffma2(acc, pk2(a, a), zv[li]);
        }
        float u, v;
        upk2(u, v, acc);
        out[k * NL + r]           = u;
        out[NF * NL + k * NL + r] = v;
    }
}

extern "C" void kernel_launch(void* const* d_in, const int* in_sizes, int n_in,
                              void* d_out, int out_size)
{
    const float* pk  = (const float*)d_in[0];
    const float* TAx = (const float*)d_in[1];
    const float* TAy = (const float*)d_in[2];
    const float* fc  = (const float*)d_in[3];
    float* out = (float*)d_out;

    eigen_kernel<<<NL, 64>>>(pk, fc);
    main2_kernel<<<GRID2, TBLK>>>(TAx, TAy, out);
}

// round 16
// speedup vs baseline: 1.1235x; 1.1235x over previous
#include <cuda_runtime.h>

#define NL     32
#define NF     720
#define DTF    60.0f
#define SCALE  256.0f
#define CHK    32          // scan chunk = transform tile (22*32 + 15 = 719)
#define NCHK   23
#define TBLK   1024
#define GRID2  24          // block 0 = modal sums+carry, blocks 1..23 = replay+transform

typedef unsigned long long u64;
#define FULL 0xffffffffu

// Persistent scratch
__device__ float    g_A  [NL * NL];   // A[l*32+r] = Q[r][l] / d_r
__device__ float2   g_Lam[NL];
__device__ float2   g_G0u[NL];        // unscaled forcing coeffs
__device__ float2   g_G1u[NL];
__device__ float    g_sc [NL];        // per-mode forcing scale (DT*Kin0*v0)
__device__ float2   g_C  [NCHK][NL];  // carries z_{32c}
__device__ unsigned g_flag;

// ---- packed f32x2 helpers ---------------------------------------------------
__device__ __forceinline__ u64 pk2(float lo, float hi) {
    u64 r; asm("mov.b64 %0, {%1, %2};" : "=l"(r) : "f"(lo), "f"(hi)); return r;
}
__device__ __forceinline__ void upk2(float& lo, float& hi, u64 v) {
    asm("mov.b64 {%0, %1}, %2;" : "=f"(lo), "=f"(hi) : "l"(v));
}
__device__ __forceinline__ void ffma2(u64& d, u64 a, u64 b) {
    asm("fma.rn.f32x2 %0, %1, %2, %3;" : "=l"(d) : "l"(a), "l"(b), "l"(d));
}
__device__ __forceinline__ float frcpa(float x) {
    float r; asm("rcp.approx.f32 %0, %1;" : "=f"(r) : "f"(x)); return r;
}
__device__ __forceinline__ float2 cmulf(float2 a, float2 b) {
    return make_float2(a.x * b.x - a.y * b.y, a.x * b.y + a.y * b.x);
}

// Sturm count with 4-step batched rescaling (sign-preserving)
__device__ __forceinline__ int sturm_count(float x,
                                           const float* __restrict__ ch,
                                           const float* __restrict__ s2h)
{
    float p0 = 1.0f;
    float p1 = ch[0] - x;
    bool  s1 = (p1 < 0.0f) || (p1 == 0.0f);
    int   cnt = s1 ? 1 : 0;
    #pragma unroll
    for (int r = 1; r < NL; ++r) {
        float p2 = fmaf(ch[r] - x, p1, -s2h[r] * p0);
        bool sg = (p2 < 0.0f);
        if (p2 == 0.0f) sg = !s1;
        cnt += (sg != s1) ? 1 : 0;
        p0 = p1; p1 = p2; s1 = sg;
        if ((r & 3) == 3) {
            float m  = fmaxf(fmaxf(fabsf(p0), fabsf(p1)), 1e-30f);
            float sc = frcpa(m);
            p0 *= sc; p1 *= sc;
        }
    }
    return cnt;
}

// ---------------------------------------------------------------------------
// Kernel 1: eigen solve. 32 blocks x 64 threads. (R14 structure, 5 rounds)
// ---------------------------------------------------------------------------
__global__ void __launch_bounds__(64, 1)
eigen_kernel(const float* __restrict__ pk, const float* __restrict__ fc)
{
    __shared__ float ch [NL];
    __shared__ float sh [NL];
    __shared__ float s2h[NL];
    __shared__ float vsm[NL];

    const int tid  = threadIdx.x;
    const int lane = tid & 31;
    const int w    = tid >> 5;
    const int l    = blockIdx.x;

    if (l == 0 && tid == 0) g_flag = 0;

    float dinv = 0.0f;
    if (w == 0) {
        const float kin  = expf(pk[2 * lane]);
        const float kout = expf(pk[2 * lane + 1]);
        float t = (lane > 0) ? 0.5f * (pk[2 * lane - 1] - pk[2 * lane]) : 0.0f;
        #pragma unroll
        for (int o = 1; o < 32; o <<= 1) {
            float u = __shfl_up_sync(FULL, t, o);
            if (lane >= o) t += u;
        }
        dinv = expf(-t);

        const float c = -DTF * (((lane > 0) ? kin : 0.0f) + kout) * SCALE;
        const float s = (lane > 0)
            ? DTF * expf(0.5f * (pk[2 * lane] + pk[2 * lane - 1])) * SCALE
            : 0.0f;
        ch[lane]  = c;
        sh[lane]  = s;
        s2h[lane] = s * s;
    }
    __syncthreads();

    // bisection (both warps, 5 rounds)
    const float c_  = ch[lane];
    const float s_  = sh[lane];
    const float op_ = (lane < NL - 1) ? sh[lane + 1] : 0.0f;
    float rad = s_ + op_;
    float lo  = c_ - rad, hi = c_ + rad;
    #pragma unroll
    for (int o = 16; o > 0; o >>= 1) {
        lo = fminf(lo, __shfl_xor_sync(FULL, lo, o));
        hi = fmaxf(hi, __shfl_xor_sync(FULL, hi, o));
    }
    float width = hi - lo;
    float a_ = lo - 1e-6f * (fabsf(width) + 1.0f);
    float b_ = hi + 1e-6f * (fabsf(width) + 1.0f);

    for (int round = 0; round < 5; ++round) {
        float x = a_ + (b_ - a_) * (float)(lane + 1) * (1.0f / 33.0f);
        int cnt = sturm_count(x, ch, s2h);
        unsigned mask = __ballot_sync(FULL, cnt <= l);
        if (mask) {
            int j = 31 - __clz((int)mask);
            float na = __shfl_sync(FULL, x, j);
            float nb = (j < 31) ? __shfl_sync(FULL, x, j + 1) : b_;
            a_ = na; b_ = nb;
        } else {
            b_ = __shfl_sync(FULL, x, 0);
        }
    }
    const float xhat = 0.5f * (a_ + b_);

    if (w == 0) {
        if (lane == 0) {
            float rp[NL];
            {
                float dd = ch[0] - xhat;
                dd = copysignf(fmaxf(fabsf(dd), 1e-12f), dd);
                rp[0] = frcpa(dd);
                #pragma unroll
                for (int r = 1; r < NL; ++r) {
                    dd = fmaf(-s2h[r], rp[r - 1], ch[r] - xhat);
                    dd = copysignf(fmaxf(fabsf(dd), 1e-12f), dd);
                    rp[r] = frcpa(dd);
                }
            }
            float vb[NL];
            #pragma unroll
            for (int r = 0; r < NL; ++r) vb[r] = 1.0f;

            #pragma unroll
            for (int it = 0; it < 2; ++it) {
                float wk[NL];
                wk[0] = vb[0];
                #pragma unroll
                for (int r = 1; r < NL; ++r)
                    wk[r] = fmaf(-sh[r] * rp[r - 1], wk[r - 1], vb[r]);
                wk[NL - 1] = wk[NL - 1] * rp[NL - 1];
                #pragma unroll
                for (int r = NL - 2; r >= 0; --r)
                    wk[r] = (wk[r] - sh[r + 1] * wk[r + 1]) * rp[r];

                float m = 1e-30f;
                #pragma unroll
                for (int r = 0; r < NL; ++r) m = fmaxf(m, fabsf(wk[r]));
                float im = frcpa(m);
                #pragma unroll
                for (int r = 0; r < NL; ++r) vb[r] = wk[r] * im;
            }
            #pragma unroll
            for (int r = 0; r < NL; ++r) vsm[r] = vb[r];
        }
        __syncwarp();

        float v  = vsm[lane];
        float n2 = v * v;
        #pragma unroll
        for (int o = 16; o > 0; o >>= 1) n2 += __shfl_xor_sync(FULL, n2, o);
        float inv = rsqrtf(n2);
        g_A[l * NL + lane] = v * inv * dinv;
        float v0n = __shfl_sync(FULL, v, 0) * inv;
        if (lane == 0) g_sc[l] = DTF * expf(pk[0]) * v0n;
    } else if (lane == 0) {
        const double mur = (double)xhat * (1.0 / (double)SCALE);
        const double mui = -(double)DTF * (double)fc[0];
        const double br  = 1.0 + mur, bi = mui;

        double b2r  = br * br - bi * bi,     b2i  = 2.0 * br * bi;
        double b4r  = b2r * b2r - b2i * b2i, b4i  = 2.0 * b2r * b2i;
        double b8r  = b4r * b4r - b4i * b4i, b8i  = 2.0 * b4r * b4i;
        double b16r = b8r * b8r - b8i * b8i, b16i = 2.0 * b8r * b8i;
        double b32r = b16r * b16r - b16i * b16i, b32i = 2.0 * b16r * b16i;

        double Lr = b32r * b16r - b32i * b16i;
        double Li = b32r * b16i + b32i * b16r;
        { double tr = Lr * b8r - Li * b8i; Li = Lr * b8i + Li * b8r; Lr = tr; }
        { double tr = Lr * b4r - Li * b4i; Li = Lr * b4i + Li * b4r; Lr = tr; }

        double mLr = mur * Lr - mui * Li;
        double mLi = mur * Li + mui * Lr;
        double n0r = 1.0 - Lr + 60.0 * mLr, n0i = -Li + 60.0 * mLi;
        double n1r = Lr - 1.0 - 60.0 * mur, n1i = Li - 60.0 * mui;
        double m2r = mur * mur - mui * mui, m2i = 2.0 * mur * mui;
        double dr  = 60.0 * m2r, di = 60.0 * m2i;
        double idn = 1.0 / (dr * dr + di * di);
        double G0r = (n0r * dr + n0i * di) * idn;
        double G0i = (n0i * dr - n0r * di) * idn;
        double G1r = (n1r * dr + n1i * di) * idn;
        double G1i = (n1i * dr - n1r * di) * idn;

        g_Lam[l] = make_float2((float)Lr,  (float)Li);
        g_G0u[l] = make_float2((float)G0r, (float)G0i);
        g_G1u[l] = make_float2((float)G1r, (float)G1i);
    }
}

// ---------------------------------------------------------------------------
// Kernel 2: block 0 = chunk sums + carry scan; blocks 1..23 = replay + transform.
// ---------------------------------------------------------------------------
__global__ void __launch_bounds__(TBLK, 1)
main2_kernel(const float* __restrict__ TAx, const float* __restrict__ TAy,
             float* __restrict__ out)
{
    const int tid = threadIdx.x;

    if (blockIdx.x == 0) {
        // ------------- modal: phase-1 sums (23 warps) + carry (warp 0) -------------
        __shared__ float  stx[NF], sty[NF];
        __shared__ float2 ssum[NCHK][NL];

        if (tid < NF) { stx[tid] = TAx[tid]; sty[tid] = TAy[tid]; }
        __syncthreads();

        const int l = tid & 31;
        const int c = tid >> 5;                    // warp = chunk

        const float2 L  = g_Lam[l];
        const float  sc = g_sc[l];
        float2 G0 = g_G0u[l]; G0.x *= sc; G0.y *= sc;
        float2 G1 = g_G1u[l]; G1.x *= sc; G1.y *= sc;

        if (c < NCHK) {
            const int k0  = c * CHK;
            const int len = min(CHK, (NF - 1) - k0);   // 32, last chunk 15
            float zr = 0.0f, zi = 0.0f;
            float txa = stx[k0], tya = sty[k0];
            #pragma unroll 4
            for (int m = 0; m < len; ++m) {
                float txb = stx[k0 + m + 1], tyb = sty[k0 + m + 1];
                float fr = txa * G0.x - tya * G0.y + txb * G1.x - tyb * G1.y;
                float fi = txa * G0.y + tya * G0.x + txb * G1.y + tyb * G1.x;
                float nr = fr + L.x * zr - L.y * zi;
                float ni = fi + L.x * zi + L.y * zr;
                zr = nr; zi = ni;
                txa = txb; tya = tyb;
            }
            ssum[c][l] = make_float2(zr, zi);
        }
        __syncthreads();

        if (c == 0) {
            // Lam^32 per mode (5 squarings)
            float2 p = L;
            #pragma unroll
            for (int q = 0; q < 5; ++q) p = cmulf(p, p);

            float kr = 0.0f, ki = 0.0f;
            g_C[0][l] = make_float2(0.0f, 0.0f);
            for (int cc = 0; cc < NCHK - 1; ++cc) {     // carries 1..22
                float2 sv = ssum[cc][l];
                float nr = p.x * kr - p.y * ki + sv.x;
                float ni = p.x * ki + p.y * kr + sv.y;
                kr = nr; ki = ni;
                g_C[cc + 1][l] = make_float2(kr, ki);
            }
            __threadfence();
            __syncwarp();
            if (l == 0) atomicExch(&g_flag, 1);
        }
    } else {
        // ------------- replay + transform (blocks 1..23) -------------
        __shared__ float  As[NL * NL];
        __shared__ __align__(16) float2 Zs[CHK][NL];
        __shared__ float  ltx[CHK + 1], lty[CHK + 1];
        __shared__ float2 Lsm[NL], G0sm[NL], G1sm[NL];

        const int kbase = (blockIdx.x - 1) * CHK;
        const int len   = min(CHK, (NF - 1) - kbase);   // 32, block 23: 15

        // pre-spin staging (all independent of the flag)
        for (int i = tid; i < NL * NL; i += TBLK) As[i] = g_A[i];
        if (tid <= len) { ltx[tid] = TAx[kbase + tid]; lty[tid] = TAy[kbase + tid]; }
        if (tid < NL) {
            const float sc = g_sc[tid];
            Lsm[tid] = g_Lam[tid];
            float2 a = g_G0u[tid]; a.x *= sc; a.y *= sc; G0sm[tid] = a;
            float2 b = g_G1u[tid]; b.x *= sc; b.y *= sc; G1sm[tid] = b;
        }
        if (blockIdx.x == 1 && tid < NL) {       // row 0 = zeros
            out[tid]           = 0.0f;
            out[NF * NL + tid] = 0.0f;
        }

        if (tid == 0)
            while (atomicAdd(&g_flag, 0) == 0) __nanosleep(32);
        __syncthreads();
        __threadfence();

        // warp 0: replay this block's steps from its carry
        if (tid < 32) {
            const int l = tid;
            const float2 L  = Lsm[l];
            const float2 G0 = G0sm[l];
            const float2 G1 = G1sm[l];
            float2 K = g_C[blockIdx.x - 1][l];
            float zr = K.x, zi = K.y;
            float txa = ltx[0], tya = lty[0];
            #pragma unroll 4
            for (int m = 0; m < len; ++m) {
                float txb = ltx[m + 1], tyb = lty[m + 1];
                float fr = txa * G0.x - tya * G0.y + txb * G1.x - tyb * G1.y;
                float fi = txa * G0.y + tya * G0.x + txb * G1.y + tyb * G1.x;
                float nr = fr + L.x * zr - L.y * zi;
                float ni = fi + L.x * zi + L.y * zr;
                zr = nr; zi = ni;
                txa = txb; tya = tyb;
                Zs[m][l] = make_float2(zr, zi);     // z_{kbase+m+1}
            }
        }
        __syncthreads();

        // transform: thread (kk, r) -> output row kbase+kk+1
        const int kk = tid >> 5, r = tid & 31;
        if (kk < len) {
            const int row = kbase + kk + 1;
            const u64* zv = reinterpret_cast<const u64*>(&Zs[kk][0]);
            u64 acc = 0ull;
            #pragma unroll
            for (int li = 0; li < NL; ++li) {
                float a = As[li * NL + r];
                ffma2(acc, pk2(a, a), zv[li]);
            }
            float u, v;
            upk2(u, v, acc);
            out[row * NL + r]           = u;
            out[NF * NL + row * NL + r] = v;
        }
    }
}

extern "C" void kernel_launch(void* const* d_in, const int* in_sizes, int n_in,
                              void* d_out, int out_size)
{
    const float* pk  = (const float*)d_in[0];
    const float* TAx = (const float*)d_in[1];
    const float* TAy = (const float*)d_in[2];
    const float* fc  = (const float*)d_in[3];
    float* out = (float*)d_out;

    eigen_kernel<<<NL, 64>>>(pk, fc);
    main2_kernel<<<GRID2, TBLK>>>(TAx, TAy, out);
}

// round 17
// speedup vs baseline: 1.1488x; 1.0225x over previous
#include <cuda_runtime.h>

#define NL     32
#define NF     720
#define DTF    60.0f
#define SCALE  256.0f
#define CHK    32          // scan chunk = transform tile (22*32 + 15 = 719)
#define NCHK   23
#define TBLK   1024
#define GRID2  24

typedef unsigned long long u64;
#define FULL 0xffffffffu

// Persistent scratch
__device__ float    g_A  [NL * NL];
__device__ float2   g_Lam[NL];
__device__ float2   g_G0u[NL];
__device__ float2   g_G1u[NL];
__device__ float    g_sc [NL];
__device__ float2   g_C  [NCHK][NL];  // carries Y_{32c} (y-space)
__device__ unsigned g_flag;

// ---- packed f32x2 helpers ---------------------------------------------------
__device__ __forceinline__ u64 pk2(float lo, float hi) {
    u64 r; asm("mov.b64 %0, {%1, %2};" : "=l"(r) : "f"(lo), "f"(hi)); return r;
}
__device__ __forceinline__ void upk2(float& lo, float& hi, u64 v) {
    asm("mov.b64 {%0, %1}, %2;" : "=f"(lo), "=f"(hi) : "l"(v));
}
__device__ __forceinline__ void ffma2(u64& d, u64 a, u64 b) {
    asm("fma.rn.f32x2 %0, %1, %2, %3;" : "=l"(d) : "l"(a), "l"(b), "l"(d));
}
__device__ __forceinline__ float frcpa(float x) {
    float r; asm("rcp.approx.f32 %0, %1;" : "=f"(r) : "f"(x)); return r;
}
__device__ __forceinline__ float2 cmulf(float2 a, float2 b) {
    return make_float2(a.x * b.x - a.y * b.y, a.x * b.y + a.y * b.x);
}

// Sturm count with 4-step batched rescaling
__device__ __forceinline__ int sturm_count(float x,
                                           const float* __restrict__ ch,
                                           const float* __restrict__ s2h)
{
    float p0 = 1.0f;
    float p1 = ch[0] - x;
    bool  s1 = (p1 < 0.0f) || (p1 == 0.0f);
    int   cnt = s1 ? 1 : 0;
    #pragma unroll
    for (int r = 1; r < NL; ++r) {
        float p2 = fmaf(ch[r] - x, p1, -s2h[r] * p0);
        bool sg = (p2 < 0.0f);
        if (p2 == 0.0f) sg = !s1;
        cnt += (sg != s1) ? 1 : 0;
        p0 = p1; p1 = p2; s1 = sg;
        if ((r & 3) == 3) {
            float m  = fmaxf(fmaxf(fabsf(p0), fabsf(p1)), 1e-30f);
            float sc = frcpa(m);
            p0 *= sc; p1 *= sc;
        }
    }
    return cnt;
}

// ---------------------------------------------------------------------------
// Kernel 1: eigen solve. 32 blocks x 64 threads. 5 bisection rounds,
// 1 inverse-iteration sweep (shift accuracy makes more redundant).
// ---------------------------------------------------------------------------
__global__ void __launch_bounds__(64, 1)
eigen_kernel(const float* __restrict__ pk, const float* __restrict__ fc)
{
    __shared__ float ch [NL];
    __shared__ float sh [NL];
    __shared__ float s2h[NL];
    __shared__ float vsm[NL];

    const int tid  = threadIdx.x;
    const int lane = tid & 31;
    const int w    = tid >> 5;
    const int l    = blockIdx.x;

    if (l == 0 && tid == 0) g_flag = 0;

    float dinv = 0.0f;
    if (w == 0) {
        const float kin  = expf(pk[2 * lane]);
        const float kout = expf(pk[2 * lane + 1]);
        float t = (lane > 0) ? 0.5f * (pk[2 * lane - 1] - pk[2 * lane]) : 0.0f;
        #pragma unroll
        for (int o = 1; o < 32; o <<= 1) {
            float u = __shfl_up_sync(FULL, t, o);
            if (lane >= o) t += u;
        }
        dinv = expf(-t);

        const float c = -DTF * (((lane > 0) ? kin : 0.0f) + kout) * SCALE;
        const float s = (lane > 0)
            ? DTF * expf(0.5f * (pk[2 * lane] + pk[2 * lane - 1])) * SCALE
            : 0.0f;
        ch[lane]  = c;
        sh[lane]  = s;
        s2h[lane] = s * s;
    }
    __syncthreads();

    // bisection (both warps, 5 rounds)
    const float c_  = ch[lane];
    const float s_  = sh[lane];
    const float op_ = (lane < NL - 1) ? sh[lane + 1] : 0.0f;
    float rad = s_ + op_;
    float lo  = c_ - rad, hi = c_ + rad;
    #pragma unroll
    for (int o = 16; o > 0; o >>= 1) {
        lo = fminf(lo, __shfl_xor_sync(FULL, lo, o));
        hi = fmaxf(hi, __shfl_xor_sync(FULL, hi, o));
    }
    float width = hi - lo;
    float a_ = lo - 1e-6f * (fabsf(width) + 1.0f);
    float b_ = hi + 1e-6f * (fabsf(width) + 1.0f);

    for (int round = 0; round < 5; ++round) {
        float x = a_ + (b_ - a_) * (float)(lane + 1) * (1.0f / 33.0f);
        int cnt = sturm_count(x, ch, s2h);
        unsigned mask = __ballot_sync(FULL, cnt <= l);
        if (mask) {
            int j = 31 - __clz((int)mask);
            float na = __shfl_sync(FULL, x, j);
            float nb = (j < 31) ? __shfl_sync(FULL, x, j + 1) : b_;
            a_ = na; b_ = nb;
        } else {
            b_ = __shfl_sync(FULL, x, 0);
        }
    }
    const float xhat = 0.5f * (a_ + b_);

    if (w == 0) {
        if (lane == 0) {
            // LU factorization (chain: fmaf + clamp + rcp per step)
            float rp[NL];
            {
                float dd = ch[0] - xhat;
                dd = copysignf(fmaxf(fabsf(dd), 1e-12f), dd);
                rp[0] = frcpa(dd);
                #pragma unroll
                for (int r = 1; r < NL; ++r) {
                    dd = fmaf(-s2h[r], rp[r - 1], ch[r] - xhat);
                    dd = copysignf(fmaxf(fabsf(dd), 1e-12f), dd);
                    rp[r] = frcpa(dd);
                }
            }
            // ONE inverse-iteration sweep from vb = ones
            float wk[NL];
            wk[0] = 1.0f;
            #pragma unroll
            for (int r = 1; r < NL; ++r)
                wk[r] = fmaf(-sh[r] * rp[r - 1], wk[r - 1], 1.0f);
            wk[NL - 1] = wk[NL - 1] * rp[NL - 1];
            #pragma unroll
            for (int r = NL - 2; r >= 0; --r)
                wk[r] = (wk[r] - sh[r + 1] * wk[r + 1]) * rp[r];
            #pragma unroll
            for (int r = 0; r < NL; ++r) vsm[r] = wk[r];
        }
        __syncwarp();

        float v  = vsm[lane];
        float n2 = v * v;
        #pragma unroll
        for (int o = 16; o > 0; o >>= 1) n2 += __shfl_xor_sync(FULL, n2, o);
        float inv = rsqrtf(n2);
        g_A[l * NL + lane] = v * inv * dinv;
        float v0n = __shfl_sync(FULL, v, 0) * inv;
        if (lane == 0) g_sc[l] = DTF * expf(pk[0]) * v0n;
    } else if (lane == 0) {
        const double mur = (double)xhat * (1.0 / (double)SCALE);
        const double mui = -(double)DTF * (double)fc[0];
        const double br  = 1.0 + mur, bi = mui;

        double b2r  = br * br - bi * bi,     b2i  = 2.0 * br * bi;
        double b4r  = b2r * b2r - b2i * b2i, b4i  = 2.0 * b2r * b2i;
        double b8r  = b4r * b4r - b4i * b4i, b8i  = 2.0 * b4r * b4i;
        double b16r = b8r * b8r - b8i * b8i, b16i = 2.0 * b8r * b8i;
        double b32r = b16r * b16r - b16i * b16i, b32i = 2.0 * b16r * b16i;

        double Lr = b32r * b16r - b32i * b16i;
        double Li = b32r * b16i + b32i * b16r;
        { double tr = Lr * b8r - Li * b8i; Li = Lr * b8i + Li * b8r; Lr = tr; }
        { double tr = Lr * b4r - Li * b4i; Li = Lr * b4i + Li * b4r; Lr = tr; }

        double mLr = mur * Lr - mui * Li;
        double mLi = mur * Li + mui * Lr;
        double n0r = 1.0 - Lr + 60.0 * mLr, n0i = -Li + 60.0 * mLi;
        double n1r = Lr - 1.0 - 60.0 * mur, n1i = Li - 60.0 * mui;
        double m2r = mur * mur - mui * mui, m2i = 2.0 * mur * mui;
        double dr  = 60.0 * m2r, di = 60.0 * m2i;
        double idn = 1.0 / (dr * dr + di * di);
        double G0r = (n0r * dr + n0i * di) * idn;
        double G0i = (n0i * dr - n0r * di) * idn;
        double G1r = (n1r * dr + n1i * di) * idn;
        double G1i = (n1i * dr - n1r * di) * idn;

        g_Lam[l] = make_float2((float)Lr,  (float)Li);
        g_G0u[l] = make_float2((float)G0r, (float)G0i);
        g_G1u[l] = make_float2((float)G1r, (float)G1i);
    }
}

// ---------------------------------------------------------------------------
// Kernel 2: y-space scan (single forcing H = G0 + L*G1).
//   block 0   : chunk sums + carry; blocks 1..23 : replay + transform
//   z_k = y_k + G1*tau_k recovered only at outputs.
// ---------------------------------------------------------------------------
__global__ void __launch_bounds__(TBLK, 1)
main2_kernel(const float* __restrict__ TAx, const float* __restrict__ TAy,
             float* __restrict__ out)
{
    const int tid = threadIdx.x;

    if (blockIdx.x == 0) {
        __shared__ __align__(8) float2 stxy[NF];
        __shared__ float2 ssum[NCHK][NL];
        __shared__ float2 Hs[NL], G1s[NL];

        if (tid < NF) stxy[tid] = make_float2(TAx[tid], TAy[tid]);
        if (tid < NL) {
            const float sc = g_sc[tid];
            float2 L  = g_Lam[tid];
            float2 g0 = g_G0u[tid];
            float2 g1 = g_G1u[tid];
            float2 h  = cmulf(L, g1);
            h.x = (h.x + g0.x) * sc;  h.y = (h.y + g0.y) * sc;
            Hs[tid]  = h;
            G1s[tid] = make_float2(g1.x * sc, g1.y * sc);
        }
        __syncthreads();

        const int l = tid & 31;
        const int c = tid >> 5;

        const float2 L = g_Lam[l];
        const float2 H = Hs[l];

        if (c < NCHK) {
            const int k0  = c * CHK;
            const int len = min(CHK, (NF - 1) - k0);
            float yr = 0.0f, yi = 0.0f;
            #pragma unroll 4
            for (int m = 0; m < len; ++m) {
                float2 t = stxy[k0 + m];
                float fr = t.x * H.x - t.y * H.y;
                float fi = t.x * H.y + t.y * H.x;
                float nr = fr + L.x * yr - L.y * yi;
                float ni = fi + L.x * yi + L.y * yr;
                yr = nr; yi = ni;
            }
            ssum[c][l] = make_float2(yr, yi);
        }
        __syncthreads();

        if (c == 0) {
            // Lam^32
            float2 p = L;
            #pragma unroll
            for (int q = 0; q < 5; ++q) p = cmulf(p, p);

            // Y_0 = -G1s * tau_0  (z_0 = 0)
            float2 t0 = stxy[0];
            float2 g1 = G1s[l];
            float kr = -(g1.x * t0.x - g1.y * t0.y);
            float ki = -(g1.x * t0.y + g1.y * t0.x);
            g_C[0][l] = make_float2(kr, ki);
            for (int cc = 0; cc < NCHK - 1; ++cc) {
                float2 sv = ssum[cc][l];
                float nr = p.x * kr - p.y * ki + sv.x;
                float ni = p.x * ki + p.y * kr + sv.y;
                kr = nr; ki = ni;
                g_C[cc + 1][l] = make_float2(kr, ki);
            }
            __threadfence();
            __syncwarp();
            if (l == 0) atomicExch(&g_flag, 1);
        }
    } else {
        __shared__ float  As[NL * NL];
        __shared__ __align__(16) float2 Zs[CHK][NL];
        __shared__ __align__(8) float2 ltxy[CHK + 1];
        __shared__ float2 Lsm[NL], Hsm[NL], G1sm[NL];

        const int kbase = (blockIdx.x - 1) * CHK;
        const int len   = min(CHK, (NF - 1) - kbase);

        // pre-spin staging
        for (int i = tid; i < NL * NL; i += TBLK) As[i] = g_A[i];
        if (tid <= len) ltxy[tid] = make_float2(TAx[kbase + tid], TAy[kbase + tid]);
        if (tid < NL) {
            const float sc = g_sc[tid];
            float2 L  = g_Lam[tid];
            float2 g0 = g_G0u[tid];
            float2 g1 = g_G1u[tid];
            float2 h  = cmulf(L, g1);
            h.x = (h.x + g0.x) * sc;  h.y = (h.y + g0.y) * sc;
            Lsm[tid]  = L;
            Hsm[tid]  = h;
            G1sm[tid] = make_float2(g1.x * sc, g1.y * sc);
        }
        if (blockIdx.x == 1 && tid < NL) {
            out[tid]           = 0.0f;
            out[NF * NL + tid] = 0.0f;
        }

        if (tid == 0)
            while (atomicAdd(&g_flag, 0) == 0) __nanosleep(32);
        __syncthreads();
        __threadfence();

        // warp 0: replay in y-space, recover z at each output
        if (tid < 32) {
            const int l = tid;
            const float2 L  = Lsm[l];
            const float2 H  = Hsm[l];
            const float2 g1 = G1sm[l];
            float2 K = g_C[blockIdx.x - 1][l];
            float yr = K.x, yi = K.y;
            #pragma unroll 4
            for (int m = 0; m < len; ++m) {
                float2 t = ltxy[m];
                float fr = t.x * H.x - t.y * H.y;
                float fi = t.x * H.y + t.y * H.x;
                float nr = fr + L.x * yr - L.y * yi;
                float ni = fi + L.x * yi + L.y * yr;
                yr = nr; yi = ni;
                float2 t1 = ltxy[m + 1];
                float zr = yr + g1.x * t1.x - g1.y * t1.y;
                float zi = yi + g1.x * t1.y + g1.y * t1.x;
                Zs[m][l] = make_float2(zr, zi);      // z_{kbase+m+1}
            }
        }
        __syncthreads();

        const int kk = tid >> 5, r = tid & 31;
        if (kk < len) {
            const int row = kbase + kk + 1;
            const u64* zv = reinterpret_cast<const u64*>(&Zs[kk][0]);
            u64 acc = 0ull;
            #pragma unroll
            for (int li = 0; li < NL; ++li) {
                float a = As[li * NL + r];
                ffma2(acc, pk2(a, a), zv[li]);
            }
            float u, v;
            upk2(u, v, acc);
            out[row * NL + r]           = u;
            out[NF * NL + row * NL + r] = v;
        }
    }
}

extern "C" void kernel_launch(void* const* d_in, const int* in_sizes, int n_in,
                              void* d_out, int out_size)
{
    const float* pk  = (const float*)d_in[0];
    const float* TAx = (const float*)d_in[1];
    const float* TAy = (const float*)d_in[2];
    const float* fc  = (const float*)d_in[3];
    float* out = (float*)d_out;

    eigen_kernel<<<NL, 64>>>(pk, fc);
    main2_kernel<<<GRID2, TBLK>>>(TAx, TAy, out);
}